// round 1
// baseline (speedup 1.0000x reference)
#include <cuda_runtime.h>

// RankingLoss, N=16384.
// loss = (1/N) * sum_i [ cnt_i>0 ? (sum_{j: t_j<t_i} max(0, 0.1 - (p_i - p_j))) / cnt_i : 0 ]

#define NN 16384
#define NJCHUNK 16
#define JCHUNK (NN / NJCHUNK)   // 1024
#define TPB 256
#define NBLKROW (NN / TPB)      // 64
#define MARGIN 0.1f

// Deterministic partial accumulators (no atomics).
__device__ float g_rowsum[NJCHUNK][NN];
__device__ float g_rowcnt[NJCHUNK][NN];
__device__ float g_partial[NBLKROW];

__global__ void __launch_bounds__(TPB)
pair_kernel(const float* __restrict__ pred, const float* __restrict__ target) {
    // Interleaved (target, pred) tile: inner loop does one broadcast LDS.64 per pair.
    __shared__ float2 sh_tp[JCHUNK];

    const int i = blockIdx.x * TPB + threadIdx.x;      // row owned by this thread
    const int jc = blockIdx.y;                         // which j-chunk
    const int jbase = jc * JCHUNK;

    // Stage the j-chunk: each thread loads one float4 of target and one of pred,
    // writes 4 interleaved float2 entries.
    {
        const float4* t4 = reinterpret_cast<const float4*>(target + jbase);
        const float4* p4 = reinterpret_cast<const float4*>(pred + jbase);
        for (int k = threadIdx.x; k < JCHUNK / 4; k += TPB) {
            float4 t = t4[k];
            float4 p = p4[k];
            sh_tp[k * 4 + 0] = make_float2(t.x, p.x);
            sh_tp[k * 4 + 1] = make_float2(t.y, p.y);
            sh_tp[k * 4 + 2] = make_float2(t.z, p.z);
            sh_tp[k * 4 + 3] = make_float2(t.w, p.w);
        }
    }
    __syncthreads();

    const float ti = target[i];
    const float si = MARGIN - pred[i];

    float sum = 0.0f;
    float cnt = 0.0f;

#pragma unroll 8
    for (int k = 0; k < JCHUNK; k++) {
        float2 tp = sh_tp[k];
        float h = fmaxf(si + tp.y, 0.0f);
        if (tp.x < ti) {
            sum += h;
            cnt += 1.0f;
        }
    }

    g_rowsum[jc][i] = sum;
    g_rowcnt[jc][i] = cnt;
}

__global__ void __launch_bounds__(TPB)
row_reduce_kernel() {
    __shared__ float sh[TPB];
    const int i = blockIdx.x * TPB + threadIdx.x;

    float s = 0.0f, c = 0.0f;
#pragma unroll
    for (int jc = 0; jc < NJCHUNK; jc++) {
        s += g_rowsum[jc][i];
        c += g_rowcnt[jc][i];
    }
    float per = (c > 0.0f) ? (s / c) : 0.0f;

    sh[threadIdx.x] = per;
    __syncthreads();
#pragma unroll
    for (int off = TPB / 2; off > 0; off >>= 1) {
        if (threadIdx.x < off) sh[threadIdx.x] += sh[threadIdx.x + off];
        __syncthreads();
    }
    if (threadIdx.x == 0) g_partial[blockIdx.x] = sh[0];
}

__global__ void final_reduce_kernel(float* __restrict__ out) {
    // Single thread, fixed order: fully deterministic.
    if (threadIdx.x == 0 && blockIdx.x == 0) {
        float t = 0.0f;
        for (int b = 0; b < NBLKROW; b++) t += g_partial[b];
        out[0] = t / (float)NN;
    }
}

extern "C" void kernel_launch(void* const* d_in, const int* in_sizes, int n_in,
                              void* d_out, int out_size) {
    const float* pred   = (const float*)d_in[0];
    const float* target = (const float*)d_in[1];
    float* out = (float*)d_out;
    (void)in_sizes; (void)n_in; (void)out_size;

    dim3 grid(NBLKROW, NJCHUNK, 1);
    pair_kernel<<<grid, TPB>>>(pred, target);
    row_reduce_kernel<<<NBLKROW, TPB>>>();
    final_reduce_kernel<<<1, 32>>>(out);
}

// round 2
// speedup vs baseline: 1.1016x; 1.1016x over previous
#include <cuda_runtime.h>

// RankingLoss, N=16384.
// loss = (1/N) * sum_i [ cnt_i>0 ? (sum_{j: t_j<t_i} max(0, 0.1 - (p_i - p_j))) / cnt_i : 0 ]
//
// Strategy: rank points by target via bucket sort (targets ~ U[0,1)).
// In target-sorted order, row r's valid set is exactly {k < r}, cnt_r = r.
// Pair phase becomes a triangular sweep: 0.5x pairs, ~3 instr/pair.

#define NN 16384
#define NBUCK 16384
#define TPB 256
#define CH 1024                 // j-chunk size in pair kernel
#define NCHUNK (NN / CH)        // 16
#define NBLKROW (NN / TPB)      // 64
#define MARGIN 0.1f

// Scratch (__device__ globals; no allocations allowed).
__device__ int   g_count[NBUCK];
__device__ int   g_cursor[NBUCK];
__device__ int   g_offsets[NBUCK + 1];
__device__ int   g_members[NN];
__device__ float g_ps[NN];                  // pred in target-sorted order
__device__ float g_part[NCHUNK][NN];        // per-(chunk,row) hinge partials
__device__ float g_blk[NBLKROW];

__device__ __forceinline__ int bucket_of(float t) {
    int b = (int)(t * (float)NBUCK);
    b = b < 0 ? 0 : (b > NBUCK - 1 ? NBUCK - 1 : b);
    return b;
}

// ---- K1: zero histogram + cursors ----
__global__ void zero_kernel() {
    int i = blockIdx.x * blockDim.x + threadIdx.x;
    if (i < NBUCK) { g_count[i] = 0; g_cursor[i] = 0; }
}

// ---- K2: histogram ----
__global__ void hist_kernel(const float* __restrict__ target) {
    int i = blockIdx.x * blockDim.x + threadIdx.x;
    if (i < NN) atomicAdd(&g_count[bucket_of(target[i])], 1);
}

// ---- K3: exclusive prefix over 16384 bucket counts (single block) ----
__global__ void __launch_bounds__(1024)
prefix_kernel() {
    __shared__ int ssum[1024];
    int t = threadIdx.x;
    int base = t * 16;
    int loc[16];
    int s = 0;
#pragma unroll
    for (int k = 0; k < 16; k++) { loc[k] = g_count[base + k]; s += loc[k]; }
    ssum[t] = s;
    __syncthreads();
#pragma unroll
    for (int off = 1; off < 1024; off <<= 1) {
        int v = (t >= off) ? ssum[t - off] : 0;
        __syncthreads();
        ssum[t] += v;
        __syncthreads();
    }
    int run = ssum[t] - s;   // exclusive prefix for this thread's 16-chunk
#pragma unroll
    for (int k = 0; k < 16; k++) { g_offsets[base + k] = run; run += loc[k]; }
    if (t == 1023) g_offsets[NBUCK] = run;
}

// ---- K4: scatter member indices into bucket segments (order arbitrary) ----
__global__ void scatter_kernel(const float* __restrict__ target) {
    int i = blockIdx.x * blockDim.x + threadIdx.x;
    if (i >= NN) return;
    int b = bucket_of(target[i]);
    int pos = g_offsets[b] + atomicAdd(&g_cursor[b], 1);
    g_members[pos] = i;
}

// ---- K5: exact rank (deterministic: order-invariant) + scatter preds ----
__global__ void rank_kernel(const float* __restrict__ pred,
                            const float* __restrict__ target) {
    int i = blockIdx.x * blockDim.x + threadIdx.x;
    if (i >= NN) return;
    float ti = target[i];
    int b = bucket_of(ti);
    int lo = g_offsets[b], hi = g_offsets[b + 1];
    int r = lo;
    for (int m = lo; m < hi; m++) {
        int j = g_members[m];
        float tj = target[j];
        if (tj < ti || (tj == ti && j < i)) r++;
    }
    g_ps[r] = pred[i];
}

// ---- K6: triangular pair sweep over target-sorted preds ----
__global__ void __launch_bounds__(TPB)
pair_kernel() {
    __shared__ float sh[CH];
    const int rb = blockIdx.x;
    const int c  = blockIdx.y;
    const int r0 = rb * TPB;
    const int diagc = r0 >> 10;        // chunk containing this block's rows
    if (c > diagc) return;

    // Stage chunk c of sorted preds (1024 floats; 1 float4 per thread).
    {
        const float4* g4 = reinterpret_cast<const float4*>(g_ps + c * CH);
        reinterpret_cast<float4*>(sh)[threadIdx.x] = g4[threadIdx.x];
    }
    __syncthreads();

    const int r = r0 + threadIdx.x;
    const float si = MARGIN - g_ps[r];
    const float4* sh4 = reinterpret_cast<const float4*>(sh);

    float acc;
    if (c < diagc) {
        // Full chunk: all 1024 k's satisfy k < r.
        float a0 = 0.f, a1 = 0.f, a2 = 0.f, a3 = 0.f;
#pragma unroll 8
        for (int k = 0; k < CH / 4; k++) {
            float4 v = sh4[k];
            a0 += fmaxf(si + v.x, 0.f);
            a1 += fmaxf(si + v.y, 0.f);
            a2 += fmaxf(si + v.z, 0.f);
            a3 += fmaxf(si + v.w, 0.f);
        }
        acc = (a0 + a1) + (a2 + a3);
    } else {
        // Diagonal chunk: only k < r, i.e. local kk < lim.
        const int lim = r - c * CH;    // in [0, 1023]
        float a0 = 0.f, a1 = 0.f, a2 = 0.f, a3 = 0.f;
        int k = 0;
        for (; k + 4 <= lim; k += 4) {
            float4 v = sh4[k >> 2];
            a0 += fmaxf(si + v.x, 0.f);
            a1 += fmaxf(si + v.y, 0.f);
            a2 += fmaxf(si + v.z, 0.f);
            a3 += fmaxf(si + v.w, 0.f);
        }
        acc = (a0 + a1) + (a2 + a3);
        for (; k < lim; k++) acc += fmaxf(si + sh[k], 0.f);
    }
    g_part[c][r] = acc;
}

// ---- K7: per-row loss + block reduce ----
__global__ void __launch_bounds__(TPB)
row_reduce_kernel() {
    __shared__ float sh[TPB];
    const int r = blockIdx.x * TPB + threadIdx.x;

    float s = 0.0f;
    const int cmax = r >> 10;          // only chunks 0..cmax were written for row r
    for (int c = 0; c <= cmax; c++) s += g_part[c][r];
    float per = (r > 0) ? (s / (float)r) : 0.0f;   // cnt_r == r (distinct targets)

    sh[threadIdx.x] = per;
    __syncthreads();
#pragma unroll
    for (int off = TPB / 2; off > 0; off >>= 1) {
        if (threadIdx.x < off) sh[threadIdx.x] += sh[threadIdx.x + off];
        __syncthreads();
    }
    if (threadIdx.x == 0) g_blk[blockIdx.x] = sh[0];
}

__global__ void final_reduce_kernel(float* __restrict__ out) {
    if (threadIdx.x == 0 && blockIdx.x == 0) {
        float t = 0.0f;
        for (int b = 0; b < NBLKROW; b++) t += g_blk[b];
        out[0] = t / (float)NN;
    }
}

extern "C" void kernel_launch(void* const* d_in, const int* in_sizes, int n_in,
                              void* d_out, int out_size) {
    const float* pred   = (const float*)d_in[0];
    const float* target = (const float*)d_in[1];
    float* out = (float*)d_out;
    (void)in_sizes; (void)n_in; (void)out_size;

    zero_kernel   <<<NBUCK / TPB, TPB>>>();
    hist_kernel   <<<NN / TPB,    TPB>>>(target);
    prefix_kernel <<<1, 1024>>>();
    scatter_kernel<<<NN / TPB,    TPB>>>(target);
    rank_kernel   <<<NN / TPB,    TPB>>>(pred, target);

    dim3 grid(NBLKROW, NCHUNK, 1);
    pair_kernel<<<grid, TPB>>>();

    row_reduce_kernel<<<NBLKROW, TPB>>>();
    final_reduce_kernel<<<1, 32>>>(out);
}